// round 7
// baseline (speedup 1.0000x reference)
#include <cuda_runtime.h>
#include <math.h>
#include <float.h>
#include <limits.h>

// Problem constants (fixed by setup_inputs)
#define BB 4
#define CC 256
#define MM 1024
#define NN 16384
#define HH 224
#define WW 224
#define HWH (HH*WW)
#define KPOOL 4
#define OH (HH/KPOOL)   // 56
#define OW (WW/KPOOL)   // 56
#define PP (OH*OW)      // 3136 pool cells
#define GG 6            // spatial grid 6x6x6
#define GC (GG*GG*GG)   // 216 cells
#define GH (1.0f/6.0f)  // cell size
#define CAP 320         // candidate smem capacity

// Scratch (zero-initialized at module load; every launch restores/overwrites)
__device__ float  g_xt[(size_t)BB * MM * CC];   // xyz_feats transposed [b][m][c]
__device__ float  g_pool[(size_t)BB * PP * CC]; // pooled accumulator [b][cell][c]
__device__ float  g_cnt[(size_t)BB * HWH];      // per-pixel point count
__device__ float4 g_cs[BB * MM];                // centers reordered by cell (x,y,z,|c|^2)
__device__ int    g_ci[BB * MM];                // original center index
__device__ int    g_cstart[BB * (GC + 1)];      // center CSR starts
__device__ float4 g_pq[(size_t)BB * NN];        // points reordered by cell (x,y,z,bitcast pix)
__device__ int    g_pstart[BB * (GC + 1)];      // point CSR starts

// ---------------------------------------------------------------------------
// Bit-exact helpers (DO NOT TOUCH — these fix the discrete selection/binning)
// ---------------------------------------------------------------------------
__device__ __forceinline__ float norm3_ref(float x, float y, float z) {
    return __fadd_rn(__fadd_rn(__fmul_rn(x, x), __fmul_rn(y, y)), __fmul_rn(z, z));
}
__device__ __forceinline__ float proj_row(float k0, float k1, float k2,
                                          float x, float y, float z) {
    return __fadd_rn(__fadd_rn(__fmul_rn(k0, x), __fmul_rn(k1, y)), __fmul_rn(k2, z));
}
__device__ __forceinline__ int pixel_of(const float* __restrict__ Km,
                                        float px, float py, float pz) {
    float uz0 = proj_row(Km[0], Km[1], Km[2], px, py, pz);
    float uz1 = proj_row(Km[3], Km[4], Km[5], px, py, pz);
    float uz2 = proj_row(Km[6], Km[7], Km[8], px, py, pz);
    float zden = fmaxf(uz2, 1e-8f);
    float uf = floorf(__fdiv_rn(uz0, zden));
    float vf = floorf(__fdiv_rn(uz1, zden));
    int u = (int)fminf(fmaxf(uf, 0.0f), (float)(WW - 1));
    int v = (int)fminf(fmaxf(vf, 0.0f), (float)(HH - 1));
    return v * WW + u;
}
__device__ __forceinline__ float dist_exact(float px, float py, float pz, float pn,
                                            float4 c) {
    float dot = fmaf(pz, c.z, fmaf(py, c.y, __fmul_rn(px, c.x)));
    return __fsub_rn(__fadd_rn(pn, c.w), __fmul_rn(2.0f, dot));
}
// Stable top-3 insert on (d, original-index): order-independent, matches top_k.
__device__ __forceinline__ void insert3(float d, int m,
                                        float& d0, float& d1, float& d2,
                                        int& i0, int& i1, int& i2) {
    if (d < d2 || (d == d2 && m < i2)) {
        if (d < d1 || (d == d1 && m < i1)) {
            d2 = d1; i2 = i1;
            if (d < d0 || (d == d0 && m < i0)) { d1 = d0; i1 = i0; d0 = d; i0 = m; }
            else                               { d1 = d;  i1 = m; }
        } else { d2 = d; i2 = m; }
    }
}
__device__ __forceinline__ void red_add_v4(float* addr, float4 v) {
    asm volatile("red.global.add.v4.f32 [%0], {%1, %2, %3, %4};"
                 :: "l"(addr), "f"(v.x), "f"(v.y), "f"(v.z), "f"(v.w)
                 : "memory");
}
__device__ __forceinline__ int cell_coord(float x) {        // x,y in [0,1)
    return min(GG - 1, max(0, (int)(x * (float)GG)));
}
__device__ __forceinline__ int cell_coord_z(float z) {      // z in [0.5,1.5)
    return min(GG - 1, max(0, (int)((z - 0.5f) * (float)GG)));
}

// ---------------------------------------------------------------------------
// Kernel 1: transpose xyz_feats [B][C][M] -> g_xt [B][M][C]
// ---------------------------------------------------------------------------
__global__ void k_transpose(const float* __restrict__ X) {
    __shared__ float tile[32][33];
    int b  = blockIdx.z;
    int m0 = blockIdx.x * 32;
    int c0 = blockIdx.y * 32;
    int tx = threadIdx.x, ty = threadIdx.y;  // block (32,8)
    #pragma unroll
    for (int k = 0; k < 32; k += 8)
        tile[ty + k][tx] = X[((size_t)b * CC + (c0 + ty + k)) * MM + (m0 + tx)];
    __syncthreads();
    #pragma unroll
    for (int k = 0; k < 32; k += 8)
        g_xt[((size_t)b * MM + (m0 + ty + k)) * CC + (c0 + tx)] = tile[tx][ty + k];
}

// ---------------------------------------------------------------------------
// Kernel 2: build per-batch CSR grid of centers. One block per batch, 1024 thr.
// ---------------------------------------------------------------------------
__global__ void __launch_bounds__(1024) k_grid(const float* __restrict__ ctr) {
    __shared__ int scan[GC];
    __shared__ int scur[GC];
    int b = blockIdx.x;
    int t = threadIdx.x;

    if (t < GC) scan[t] = 0;
    __syncthreads();

    float x = ctr[((size_t)b * MM + t) * 3 + 0];
    float y = ctr[((size_t)b * MM + t) * 3 + 1];
    float z = ctr[((size_t)b * MM + t) * 3 + 2];
    int cell = (cell_coord_z(z) * GG + cell_coord(y)) * GG + cell_coord(x);
    atomicAdd(&scan[cell], 1);
    __syncthreads();

    for (int off = 1; off < GC; off <<= 1) {
        int add = 0;
        if (t < GC && t >= off) add = scan[t - off];
        __syncthreads();
        if (t < GC) scan[t] += add;
        __syncthreads();
    }
    if (t < GC) {
        int st = (t == 0) ? 0 : scan[t - 1];
        scur[t] = st;
        g_cstart[b * (GC + 1) + t] = st;
        if (t == 0) g_cstart[b * (GC + 1) + GC] = MM;
    }
    __syncthreads();

    int pos = atomicAdd(&scur[cell], 1);
    g_cs[b * MM + pos] = make_float4(x, y, z, norm3_ref(x, y, z));
    g_ci[b * MM + pos] = t;
}

// ---------------------------------------------------------------------------
// Kernel 3: counting-sort points by cell + per-pixel counts.
// One block per batch, 1024 threads, 16 points/thread.
// ---------------------------------------------------------------------------
__global__ void __launch_bounds__(1024) k_psort(
    const float* __restrict__ pts, const float* __restrict__ Km)
{
    __shared__ int scan[GC];
    __shared__ int scur[GC];
    int b = blockIdx.x;
    int t = threadIdx.x;

    if (t < GC) scan[t] = 0;
    __syncthreads();

    #pragma unroll
    for (int k = 0; k < NN / 1024; k++) {
        int n = k * 1024 + t;
        const float* p = &pts[((size_t)b * NN + n) * 3];
        float x = __ldg(&p[0]), y = __ldg(&p[1]), z = __ldg(&p[2]);
        int cell = (cell_coord_z(z) * GG + cell_coord(y)) * GG + cell_coord(x);
        atomicAdd(&scan[cell], 1);
        int pix = pixel_of(Km, x, y, z);
        atomicAdd(&g_cnt[(size_t)b * HWH + pix], 1.0f);
    }
    __syncthreads();

    for (int off = 1; off < GC; off <<= 1) {
        int add = 0;
        if (t < GC && t >= off) add = scan[t - off];
        __syncthreads();
        if (t < GC) scan[t] += add;
        __syncthreads();
    }
    if (t < GC) {
        int st = (t == 0) ? 0 : scan[t - 1];
        scur[t] = st;
        g_pstart[b * (GC + 1) + t] = st;
        if (t == 0) g_pstart[b * (GC + 1) + GC] = NN;
    }
    __syncthreads();

    #pragma unroll
    for (int k = 0; k < NN / 1024; k++) {
        int n = k * 1024 + t;
        const float* p = &pts[((size_t)b * NN + n) * 3];
        float x = __ldg(&p[0]), y = __ldg(&p[1]), z = __ldg(&p[2]);
        int cell = (cell_coord_z(z) * GG + cell_coord(y)) * GG + cell_coord(x);
        int pix = pixel_of(Km, x, y, z);
        int pos = atomicAdd(&scur[cell], 1);
        g_pq[(size_t)b * NN + pos] = make_float4(x, y, z, __int_as_float(pix));
    }
}

// ---------------------------------------------------------------------------
// Kernel 4: block-per-cell exact 3-NN over uniform smem candidate list,
// then warp-cooperative gather + v4 scatter. grid (GC, BB), block 128.
// ---------------------------------------------------------------------------
__global__ void __launch_bounds__(128) k_knn_scatter() {
    __shared__ float4 scand[CAP];
    __shared__ int    scidx[CAP];
    __shared__ int4   stg_i[128];
    __shared__ float4 stg_w[128];

    int cellId = blockIdx.x;
    int b      = blockIdx.y;
    int tid    = threadIdx.x;
    int lane   = tid & 31;

    int cz = cellId / (GG * GG);
    int rem = cellId % (GG * GG);
    int cy = rem / GG, cx = rem % GG;
    int x0 = max(0, cx - 1), x1 = min(GG - 1, cx + 1);
    int y0 = max(0, cy - 1), y1 = min(GG - 1, cy + 1);
    int z0 = max(0, cz - 1), z1 = min(GG - 1, cz + 1);

    // cooperative candidate load (uniform control flow; offsets computed by all)
    const int* cst = &g_cstart[b * (GC + 1)];
    int offset = 0;
    for (int zz = z0; zz <= z1; zz++) {
        for (int yy = y0; yy <= y1; yy++) {
            int rowbase = (zz * GG + yy) * GG;
            int jb = __ldg(&cst[rowbase + x0]);
            int je = __ldg(&cst[rowbase + x1 + 1]);
            int len = je - jb;
            if (offset + len <= CAP) {
                for (int i = tid; i < len; i += 128) {
                    scand[offset + i] = g_cs[b * MM + jb + i];
                    scidx[offset + i] = g_ci[b * MM + jb + i];
                }
            }
            offset += len;
        }
    }
    int ncand = offset;            // uniform across block
    bool overflow = (ncand > CAP); // ~never
    __syncthreads();

    int ps = __ldg(&g_pstart[b * (GC + 1) + cellId]);
    int pe = __ldg(&g_pstart[b * (GC + 1) + cellId + 1]);
    int nPts = pe - ps;

    const float4* xt4 = reinterpret_cast<const float4*>(g_xt);

    for (int base = 0; base < nPts; base += 128) {
        int ip = base + tid;
        if (ip < nPts) {
            float4 q = g_pq[(size_t)b * NN + ps + ip];
            float px = q.x, py = q.y, pz = q.z;
            int pix = __float_as_int(q.w);
            float pn = norm3_ref(px, py, pz);

            float d0 = FLT_MAX, d1 = FLT_MAX, d2 = FLT_MAX;
            int   i0 = INT_MAX, i1 = INT_MAX, i2 = INT_MAX;

            if (!overflow) {
                for (int j = 0; j < ncand; j++) {   // uniform trip count
                    float d = dist_exact(px, py, pz, pn, scand[j]);
                    insert3(d, scidx[j], d0, d1, d2, i0, i1, i2);
                }
            }
            // geometric completeness bound
            float bxl = (x0 > 0)      ? (px - (float)x0 * GH)                : FLT_MAX;
            float bxh = (x1 < GG - 1) ? ((float)(x1 + 1) * GH - px)          : FLT_MAX;
            float byl = (y0 > 0)      ? (py - (float)y0 * GH)                : FLT_MAX;
            float byh = (y1 < GG - 1) ? ((float)(y1 + 1) * GH - py)          : FLT_MAX;
            float bzl = (z0 > 0)      ? (pz - (0.5f + (float)z0 * GH))       : FLT_MAX;
            float bzh = (z1 < GG - 1) ? ((0.5f + (float)(z1 + 1) * GH) - pz) : FLT_MAX;
            float bound = fminf(fminf(fminf(bxl, bxh), fminf(byl, byh)), fminf(bzl, bzh));
            float boundsq = (bound >= 1e18f) ? FLT_MAX : bound * bound - 1e-5f;

            if (overflow || !(d2 < boundsq)) {
                // ~never taken (P ~ 5e-7): full exact rescan from L2
                d0 = d1 = d2 = FLT_MAX; i0 = i1 = i2 = INT_MAX;
                for (int j = 0; j < MM; j++) {
                    float d = dist_exact(px, py, pz, pn, __ldg(&g_cs[b * MM + j]));
                    insert3(d, __ldg(&g_ci[b * MM + j]), d0, d1, d2, i0, i1, i2);
                }
            }

            float w0 = __fdiv_rn(1.0f, __fadd_rn(d0, 1e-8f));
            float w1 = __fdiv_rn(1.0f, __fadd_rn(d1, 1e-8f));
            float w2 = __fdiv_rn(1.0f, __fadd_rn(d2, 1e-8f));
            float ws = __fadd_rn(__fadd_rn(w0, w1), w2);
            w0 = __fdiv_rn(w0, ws); w1 = __fdiv_rn(w1, ws); w2 = __fdiv_rn(w2, ws);

            float cnt = g_cnt[(size_t)b * HWH + pix];
            float scale = __fdiv_rn(1.0f, cnt) * 0.0625f;
            int v = pix / WW, u = pix % WW;
            int pcell = (v >> 2) * OW + (u >> 2);
            int dstBase = (b * PP + pcell) * CC;

            stg_i[tid] = make_int4(i0, i1, i2, dstBase);
            stg_w[tid] = make_float4(w0 * scale, w1 * scale, w2 * scale, 0.0f);
        }
        __syncthreads();

        int nAct = min(128, nPts - base);
        int wbase = tid & ~31;
        int wcnt = min(max(nAct - wbase, 0), 32);
        for (int k = 0; k < wcnt; k++) {
            int4   si = stg_i[wbase + k];   // broadcast
            float4 sw = stg_w[wbase + k];
            const float4* r0 = xt4 + ((size_t)b * MM + si.x) * (CC / 4);
            const float4* r1 = xt4 + ((size_t)b * MM + si.y) * (CC / 4);
            const float4* r2 = xt4 + ((size_t)b * MM + si.z) * (CC / 4);
            float* dp = &g_pool[si.w];
            #pragma unroll
            for (int j = 0; j < 2; j++) {
                int c4 = j * 32 + lane;
                float4 a  = __ldg(&r0[c4]);
                float4 bq = __ldg(&r1[c4]);
                float4 cq = __ldg(&r2[c4]);
                float4 f;
                f.x = fmaf(sw.x, a.x, fmaf(sw.y, bq.x, sw.z * cq.x));
                f.y = fmaf(sw.x, a.y, fmaf(sw.y, bq.y, sw.z * cq.y));
                f.z = fmaf(sw.x, a.z, fmaf(sw.y, bq.z, sw.z * cq.z));
                f.w = fmaf(sw.x, a.w, fmaf(sw.y, bq.w, sw.z * cq.w));
                red_add_v4(dp + c4 * 4, f);
            }
        }
        __syncthreads();
    }
}

// ---------------------------------------------------------------------------
// Kernel 5: vectorized transpose g_pool [b][p][c] -> out [b][c][p] + clear.
// ---------------------------------------------------------------------------
__global__ void __launch_bounds__(256) k_pool_out(float* __restrict__ out) {
    __shared__ float tile[64][65];
    int b  = blockIdx.z;
    int c0 = blockIdx.y * 64;
    int p0 = blockIdx.x * 64;
    int tid = threadIdx.x;

    float4 v[4];
    #pragma unroll
    for (int r = 0; r < 4; r++) {
        int w = tid + 256 * r;
        int cell = w >> 4, c4 = w & 15;
        size_t idx = ((size_t)b * PP + p0 + cell) * CC + c0 + c4 * 4;
        v[r] = *reinterpret_cast<const float4*>(&g_pool[idx]);
    }
    const float4 z4 = make_float4(0.f, 0.f, 0.f, 0.f);
    #pragma unroll
    for (int r = 0; r < 4; r++) {
        int w = tid + 256 * r;
        int cell = w >> 4, c4 = w & 15;
        size_t idx = ((size_t)b * PP + p0 + cell) * CC + c0 + c4 * 4;
        *reinterpret_cast<float4*>(&g_pool[idx]) = z4;
        tile[cell][c4 * 4 + 0] = v[r].x;
        tile[cell][c4 * 4 + 1] = v[r].y;
        tile[cell][c4 * 4 + 2] = v[r].z;
        tile[cell][c4 * 4 + 3] = v[r].w;
    }
    if (blockIdx.y == 0) {
        #pragma unroll
        for (int k = 0; k < 4; k++) {
            int i = blockIdx.x * 256 + tid + k * (49 * 256);
            g_cnt[(size_t)b * HWH + i] = 0.0f;   // 49*256*4 = 50176 = HWH
        }
    }
    __syncthreads();

    #pragma unroll
    for (int r = 0; r < 4; r++) {
        int w = tid + 256 * r;
        int c = w >> 4, p4 = w & 15;
        float4 f;
        f.x = tile[p4 * 4 + 0][c];
        f.y = tile[p4 * 4 + 1][c];
        f.z = tile[p4 * 4 + 2][c];
        f.w = tile[p4 * 4 + 3][c];
        *reinterpret_cast<float4*>(&out[((size_t)b * CC + c0 + c) * PP + p0 + p4 * 4]) = f;
    }
}

// ---------------------------------------------------------------------------
extern "C" void kernel_launch(void* const* d_in, const int* in_sizes, int n_in,
                              void* d_out, int out_size) {
    const float* feats = (const float*)d_in[0];  // [B][C][M]
    const float* pts   = (const float*)d_in[1];  // [B][N][3]
    const float* ctr   = (const float*)d_in[2];  // [B][M][3]
    const float* Km    = (const float*)d_in[3];  // [3][3]
    float* out = (float*)d_out;

    k_transpose<<<dim3(MM / 32, CC / 32, BB), dim3(32, 8)>>>(feats);
    k_grid<<<BB, 1024>>>(ctr);
    k_psort<<<BB, 1024>>>(pts, Km);
    k_knn_scatter<<<dim3(GC, BB), 128>>>();
    k_pool_out<<<dim3(PP / 64, CC / 64, BB), 256>>>(out);
}

// round 8
// speedup vs baseline: 2.3725x; 2.3725x over previous
#include <cuda_runtime.h>
#include <math.h>
#include <float.h>

// Problem constants (fixed by setup_inputs)
#define BB 4
#define CC 256
#define MM 1024
#define NN 16384
#define HH 224
#define WW 224
#define HWH (HH*WW)
#define KPOOL 4
#define OH (HH/KPOOL)   // 56
#define OW (WW/KPOOL)   // 56
#define PP (OH*OW)      // 3136 pool cells

// Scratch (zero-initialized at module load; every launch restores zeros)
__device__ float g_xt[(size_t)BB * MM * CC];    // xyz_feats transposed [b][m][c] (4MB)
__device__ float g_pool[(size_t)BB * PP * CC];  // pooled accumulator [b][cell][c] (12.8MB)
__device__ float g_cnt[(size_t)BB * HWH];       // per-pixel point count (800KB)

// ---------------------------------------------------------------------------
// Bit-exact helpers (DO NOT TOUCH — these fix the discrete selection/binning)
// ---------------------------------------------------------------------------
__device__ __forceinline__ float norm3_ref(float x, float y, float z) {
    return __fadd_rn(__fadd_rn(__fmul_rn(x, x), __fmul_rn(y, y)), __fmul_rn(z, z));
}
// Projection row: NO-FMA ascending chain (matches XLA elementwise lowering)
__device__ __forceinline__ float proj_row(float k0, float k1, float k2,
                                          float x, float y, float z) {
    return __fadd_rn(__fadd_rn(__fmul_rn(k0, x), __fmul_rn(k1, y)), __fmul_rn(k2, z));
}
__device__ __forceinline__ int pixel_of(const float* __restrict__ Km,
                                        float px, float py, float pz) {
    float uz0 = proj_row(Km[0], Km[1], Km[2], px, py, pz);
    float uz1 = proj_row(Km[3], Km[4], Km[5], px, py, pz);
    float uz2 = proj_row(Km[6], Km[7], Km[8], px, py, pz);
    float zden = fmaxf(uz2, 1e-8f);
    float uf = floorf(__fdiv_rn(uz0, zden));
    float vf = floorf(__fdiv_rn(uz1, zden));
    int u = (int)fminf(fmaxf(uf, 0.0f), (float)(WW - 1));
    int v = (int)fminf(fmaxf(vf, 0.0f), (float)(HH - 1));
    return v * WW + u;
}
__device__ __forceinline__ float dist_exact(float px, float py, float pz, float pn,
                                            float4 c) {
    float dot = fmaf(pz, c.z, fmaf(py, c.y, __fmul_rn(px, c.x)));
    return __fsub_rn(__fadd_rn(pn, c.w), __fmul_rn(2.0f, dot));
}
__device__ __forceinline__ void red_add_v4(float* addr, float4 v) {
    asm volatile("red.global.add.v4.f32 [%0], {%1, %2, %3, %4};"
                 :: "l"(addr), "f"(v.x), "f"(v.y), "f"(v.z), "f"(v.w)
                 : "memory");
}

// ---------------------------------------------------------------------------
// Kernel 1: transpose xyz_feats [B][C][M] -> g_xt [B][M][C]
// ---------------------------------------------------------------------------
__global__ void k_transpose(const float* __restrict__ X) {
    __shared__ float tile[32][33];
    int b  = blockIdx.z;
    int m0 = blockIdx.x * 32;
    int c0 = blockIdx.y * 32;
    int tx = threadIdx.x, ty = threadIdx.y;  // block (32,8)
    #pragma unroll
    for (int k = 0; k < 32; k += 8)
        tile[ty + k][tx] = X[((size_t)b * CC + (c0 + ty + k)) * MM + (m0 + tx)];
    __syncthreads();
    #pragma unroll
    for (int k = 0; k < 32; k += 8)
        g_xt[((size_t)b * MM + (m0 + ty + k)) * CC + (c0 + tx)] = tile[tx][ty + k];
}

// ---------------------------------------------------------------------------
// Kernel 2: per-pixel point counts (tiny)
// ---------------------------------------------------------------------------
__global__ void __launch_bounds__(256) k_count(
    const float* __restrict__ pts, const float* __restrict__ Km)
{
    int b = blockIdx.y;
    int n = blockIdx.x * 256 + threadIdx.x;
    const float* p = &pts[((size_t)b * NN + n) * 3];
    int pix = pixel_of(Km, p[0], p[1], p[2]);
    atomicAdd(&g_cnt[(size_t)b * HWH + pix], 1.0f);
}

// ---------------------------------------------------------------------------
// Kernel 3: dense thread-per-point 3-NN (unrolled, uniform), then
// warp-cooperative gather + v4 scatter into the pooled accumulator.
// ---------------------------------------------------------------------------
__global__ void __launch_bounds__(256) k_knn_scatter(
    const float* __restrict__ pts,   // [B][N][3]
    const float* __restrict__ ctr,   // [B][M][3]
    const float* __restrict__ Km)    // [3][3]
{
    __shared__ float4 sc[MM];        // centers (x,y,z,|c|^2)  16KB
    __shared__ int4   stg_i[256];    // (i0,i1,i2,dstCellBase) 4KB
    __shared__ float4 stg_w[256];    // (w0s,w1s,w2s,-)        4KB

    int b   = blockIdx.y;
    int tid = threadIdx.x;
    int lane = tid & 31;

    for (int i = tid; i < MM; i += 256) {
        float x = ctr[((size_t)b * MM + i) * 3 + 0];
        float y = ctr[((size_t)b * MM + i) * 3 + 1];
        float z = ctr[((size_t)b * MM + i) * 3 + 2];
        sc[i] = make_float4(x, y, z, norm3_ref(x, y, z));
    }
    __syncthreads();

    int n = blockIdx.x * 256 + tid;   // grid.x = NN/256 -> exact
    const float* p = &pts[((size_t)b * NN + n) * 3];
    float px = p[0], py = p[1], pz = p[2];
    float pn = norm3_ref(px, py, pz);

    // ---- dense top-3: strict-<, ascending m (ties -> earliest index) ----
    float d0 = FLT_MAX, d1 = FLT_MAX, d2 = FLT_MAX;
    int   i0 = 0, i1 = 0, i2 = 0;
    #pragma unroll 4
    for (int m = 0; m < MM; m++) {
        float d = dist_exact(px, py, pz, pn, sc[m]);   // broadcast LDS.128
        if (d < d2) {
            if (d < d1) {
                d2 = d1; i2 = i1;
                if (d < d0) { d1 = d0; i1 = i0; d0 = d; i0 = m; }
                else        { d1 = d;  i1 = m; }
            } else { d2 = d; i2 = m; }
        }
    }

    // ---- weights (exact IEEE divisions) ----
    float w0 = __fdiv_rn(1.0f, __fadd_rn(d0, 1e-8f));
    float w1 = __fdiv_rn(1.0f, __fadd_rn(d1, 1e-8f));
    float w2 = __fdiv_rn(1.0f, __fadd_rn(d2, 1e-8f));
    float ws = __fadd_rn(__fadd_rn(w0, w1), w2);
    w0 = __fdiv_rn(w0, ws); w1 = __fdiv_rn(w1, ws); w2 = __fdiv_rn(w2, ws);

    // ---- pixel + per-point scale = (1/count) * (1/16) ----
    int pix = pixel_of(Km, px, py, pz);
    float cnt = g_cnt[(size_t)b * HWH + pix];
    float scale = __fdiv_rn(1.0f, cnt) * 0.0625f;
    int v = pix / WW, u = pix % WW;
    int cell = (v >> 2) * OW + (u >> 2);
    int dstBase = (b * PP + cell) * CC;

    stg_i[tid] = make_int4(i0, i1, i2, dstBase);
    stg_w[tid] = make_float4(w0 * scale, w1 * scale, w2 * scale, 0.0f);
    __syncwarp();

    // ---- warp-cooperative gather + vector scatter ----
    const float4* xt4 = reinterpret_cast<const float4*>(g_xt);
    int wbase = tid & ~31;
    #pragma unroll 1
    for (int k = 0; k < 32; k++) {
        int4   si = stg_i[wbase + k];   // broadcast
        float4 sw = stg_w[wbase + k];
        const float4* r0 = xt4 + ((size_t)b * MM + si.x) * (CC / 4);
        const float4* r1 = xt4 + ((size_t)b * MM + si.y) * (CC / 4);
        const float4* r2 = xt4 + ((size_t)b * MM + si.z) * (CC / 4);
        float* dp = &g_pool[si.w];
        #pragma unroll
        for (int j = 0; j < 2; j++) {
            int c4 = j * 32 + lane;
            float4 a  = __ldg(&r0[c4]);
            float4 bq = __ldg(&r1[c4]);
            float4 cq = __ldg(&r2[c4]);
            float4 f;
            f.x = fmaf(sw.x, a.x, fmaf(sw.y, bq.x, sw.z * cq.x));
            f.y = fmaf(sw.x, a.y, fmaf(sw.y, bq.y, sw.z * cq.y));
            f.z = fmaf(sw.x, a.z, fmaf(sw.y, bq.z, sw.z * cq.z));
            f.w = fmaf(sw.x, a.w, fmaf(sw.y, bq.w, sw.z * cq.w));
            red_add_v4(dp + c4 * 4, f);
        }
    }
}

// ---------------------------------------------------------------------------
// Kernel 4: vectorized transpose g_pool [b][p][c] -> out [b][c][p] + clear.
// Tile: 64 cells x 64 channels. grid (49, 4, 4); block 256.
// ---------------------------------------------------------------------------
__global__ void __launch_bounds__(256) k_pool_out(float* __restrict__ out) {
    __shared__ float tile[64][65];
    int b  = blockIdx.z;
    int c0 = blockIdx.y * 64;
    int p0 = blockIdx.x * 64;
    int tid = threadIdx.x;

    float4 v[4];
    #pragma unroll
    for (int r = 0; r < 4; r++) {
        int w = tid + 256 * r;
        int cell = w >> 4, c4 = w & 15;
        size_t idx = ((size_t)b * PP + p0 + cell) * CC + c0 + c4 * 4;
        v[r] = *reinterpret_cast<const float4*>(&g_pool[idx]);
    }
    const float4 z4 = make_float4(0.f, 0.f, 0.f, 0.f);
    #pragma unroll
    for (int r = 0; r < 4; r++) {
        int w = tid + 256 * r;
        int cell = w >> 4, c4 = w & 15;
        size_t idx = ((size_t)b * PP + p0 + cell) * CC + c0 + c4 * 4;
        *reinterpret_cast<float4*>(&g_pool[idx]) = z4;   // restore invariant
        tile[cell][c4 * 4 + 0] = v[r].x;
        tile[cell][c4 * 4 + 1] = v[r].y;
        tile[cell][c4 * 4 + 2] = v[r].z;
        tile[cell][c4 * 4 + 3] = v[r].w;
    }
    if (blockIdx.y == 0) {
        #pragma unroll
        for (int k = 0; k < 4; k++) {
            int i = blockIdx.x * 256 + tid + k * (49 * 256);
            g_cnt[(size_t)b * HWH + i] = 0.0f;   // 49*256*4 = 50176 = HWH
        }
    }
    __syncthreads();

    #pragma unroll
    for (int r = 0; r < 4; r++) {
        int w = tid + 256 * r;
        int c = w >> 4, p4 = w & 15;
        float4 f;
        f.x = tile[p4 * 4 + 0][c];
        f.y = tile[p4 * 4 + 1][c];
        f.z = tile[p4 * 4 + 2][c];
        f.w = tile[p4 * 4 + 3][c];
        *reinterpret_cast<float4*>(&out[((size_t)b * CC + c0 + c) * PP + p0 + p4 * 4]) = f;
    }
}

// ---------------------------------------------------------------------------
extern "C" void kernel_launch(void* const* d_in, const int* in_sizes, int n_in,
                              void* d_out, int out_size) {
    const float* feats = (const float*)d_in[0];  // [B][C][M]
    const float* pts   = (const float*)d_in[1];  // [B][N][3]
    const float* ctr   = (const float*)d_in[2];  // [B][M][3]
    const float* Km    = (const float*)d_in[3];  // [3][3]
    float* out = (float*)d_out;

    k_transpose<<<dim3(MM / 32, CC / 32, BB), dim3(32, 8)>>>(feats);
    k_count<<<dim3(NN / 256, BB), 256>>>(pts, Km);
    k_knn_scatter<<<dim3(NN / 256, BB), 256>>>(pts, ctr, Km);
    k_pool_out<<<dim3(PP / 64, CC / 64, BB), 256>>>(out);
}